// round 1
// baseline (speedup 1.0000x reference)
#include <cuda_runtime.h>
#include <math.h>

// Problem constants (from reference): B=64, N=1024, D=8, S=16, DS=128
#define N_NEUR  1024
#define DS      128
#define I_CHUNK 64                       // rows of x[b] staged per smem chunk (32 KB)
#define NCHUNK  (N_NEUR / I_CHUNK)       // 16
#define MAXI    N_NEUR                   // worst-case nonzeros per row

#define KO      8                        // o's per warp
#define WARPS   8
#define OTILE   (KO * WARPS)             // 64 o's per CTA

// Scratch: sparse index lists (rebuilt every launch — no caching allowed)
__device__ int g_idx[N_NEUR * MAXI];               // 4 MB
__device__ int g_starts[N_NEUR * (NCHUNK + 1)];    // per-row chunk offsets

// ---------------------------------------------------------------------------
// Kernel 1: ballot-compact the 0/1 connectivity matrix into per-row ascending
// index lists + per-chunk start offsets. One warp per output row. Deterministic.
// ---------------------------------------------------------------------------
__global__ void build_lists(const float* __restrict__ M)
{
    int o    = blockIdx.x * (blockDim.x >> 5) + (threadIdx.x >> 5);
    int lane = threadIdx.x & 31;
    if (o >= N_NEUR) return;

    int pos = 0;
    for (int base = 0; base < N_NEUR; base += 32) {
        if (lane == 0 && (base % I_CHUNK) == 0)
            g_starts[o * (NCHUNK + 1) + base / I_CHUNK] = pos;
        float v = M[o * N_NEUR + base + lane];
        unsigned bal = __ballot_sync(0xffffffffu, v != 0.0f);
        if (v != 0.0f) {
            int rank = __popc(bal & ((1u << lane) - 1u));
            g_idx[o * MAXI + pos + rank] = base + lane;
        }
        pos += __popc(bal);
    }
    if (lane == 0) g_starts[o * (NCHUNK + 1) + NCHUNK] = pos;
}

// ---------------------------------------------------------------------------
// Kernel 2: sparse gather-sum + fused dendrite/soma epilogue.
// Grid: (N/OTILE, B). Block: 256 threads (8 warps x 8 o's each).
// Each warp reads full 512B rows from smem (32 lanes x float4, conflict-free),
// accumulating xm[b,o,0:128] as one float4 per lane per o.
// ---------------------------------------------------------------------------
__global__ void __launch_bounds__(256) neuron_kernel(
    const float* __restrict__ x,        // [B, N, D, S] = [B, N, 128]
    const float* __restrict__ w_syn,    // [N, D, S] = [N, 128]
    const float* __restrict__ b_dend,   // [N, D]
    const float* __restrict__ w_dend,   // [N, D]
    const float* __restrict__ b_soma,   // [N]
    float* __restrict__ out)            // [B, N]
{
    __shared__ float4 sx[I_CHUNK * 32];  // 32 KB: I_CHUNK rows x 128 floats

    const int b    = blockIdx.y;
    const int warp = threadIdx.x >> 5;
    const int lane = threadIdx.x & 31;
    const int o0   = blockIdx.x * OTILE + warp * KO;

    float4 acc[KO];
#pragma unroll
    for (int k = 0; k < KO; k++) acc[k] = make_float4(0.f, 0.f, 0.f, 0.f);

    const float4* xb = (const float4*)x + (size_t)b * N_NEUR * 32;

    for (int c = 0; c < NCHUNK; c++) {
        __syncthreads();   // previous chunk's readers done before overwrite
        // Stage x[b, c*64 : (c+1)*64, :] — contiguous 32 KB, coalesced float4
        const float4* src = xb + c * I_CHUNK * 32;
#pragma unroll
        for (int j = threadIdx.x; j < I_CHUNK * 32; j += 256)
            sx[j] = src[j];
        __syncthreads();

        const int cbase = c * I_CHUNK;
#pragma unroll
        for (int k = 0; k < KO; k++) {
            const int o  = o0 + k;
            const int p0 = g_starts[o * (NCHUNK + 1) + c];
            const int p1 = g_starts[o * (NCHUNK + 1) + c + 1];
            const int* lst = g_idx + o * MAXI;
            float4 a = acc[k];
            for (int p = p0; p < p1; p++) {
                int r = lst[p] - cbase;             // uniform across warp (L1 bcast)
                float4 v = sx[r * 32 + lane];       // 512B row, conflict-free
                a.x += v.x; a.y += v.y; a.z += v.z; a.w += v.w;
            }
            acc[k] = a;
        }
    }

    // Fused epilogue. lane covers elements [4*lane, 4*lane+4) of the 128-vector;
    // all 4 elements share dendrite d = lane/4 (16 s's per d, 4 lanes per d).
    const int d = lane >> 2;
#pragma unroll
    for (int k = 0; k < KO; k++) {
        const int o = o0 + k;
        float4 w = ((const float4*)w_syn)[o * 32 + lane];
        float t = acc[k].x * w.x + acc[k].y * w.y + acc[k].z * w.z + acc[k].w * w.w;
        // reduce the 4 lanes of this dendrite group -> t[d] replicated in group
        t += __shfl_xor_sync(0xffffffffu, t, 1);
        t += __shfl_xor_sync(0xffffffffu, t, 2);
        float dend = tanhf(t + b_dend[o * 8 + d]);
        float sp = dend * w_dend[o * 8 + d];
        // xor 4,8,16 sums exactly once over the 8 dendrite groups
        sp += __shfl_xor_sync(0xffffffffu, sp, 4);
        sp += __shfl_xor_sync(0xffffffffu, sp, 8);
        sp += __shfl_xor_sync(0xffffffffu, sp, 16);
        if (lane == 0) {
            float s = sp + b_soma[o];
            out[b * N_NEUR + o] = 1.0f / (1.0f + expf(-s));
        }
    }
}

// ---------------------------------------------------------------------------
extern "C" void kernel_launch(void* const* d_in, const int* in_sizes, int n_in,
                              void* d_out, int out_size)
{
    const float* x      = (const float*)d_in[0];   // [B, N, D, S]
    const float* M      = (const float*)d_in[1];   // [N, N]
    const float* w_syn  = (const float*)d_in[2];   // [N, D, S]
    const float* b_dend = (const float*)d_in[3];   // [N, D]
    const float* w_dend = (const float*)d_in[4];   // [N, D]
    const float* b_soma = (const float*)d_in[5];   // [N]
    float* out          = (float*)d_out;           // [B, N]

    const int B = in_sizes[0] / (N_NEUR * DS);     // 64

    // Rebuild sparse lists every call (determinism rule: no caching).
    build_lists<<<N_NEUR / 8, 256>>>(M);

    dim3 grid(N_NEUR / OTILE, B);                  // (16, 64)
    neuron_kernel<<<grid, 256>>>(x, w_syn, b_dend, w_dend, b_soma, out);
}

// round 3
// speedup vs baseline: 3.3857x; 3.3857x over previous
#include <cuda_runtime.h>
#include <cuda_fp16.h>
#include <math.h>
#include <stdint.h>

// Problem constants: B=64, N=1024, D=8, S=16 -> DS=128, K=1024
#define NN    1024
#define BB    64
#define DS    128
#define KDIM  1024
#define CHUNK 64                 // K per pipeline stage (64 halves = 128B rows)
#define NCH   (KDIM / CHUNK)     // 16

#define SWZ(off) ((off) ^ (((off) >> 3) & 0x70))   // SW128: bits[6:4] ^= bits[9:7]

__device__ __forceinline__ uint32_t smem_u32(const void* p) {
    uint32_t a;
    asm("{ .reg .u64 t; cvta.to.shared.u64 t, %1; cvt.u32.u64 %0, t; }" : "=r"(a) : "l"(p));
    return a;
}
__device__ __forceinline__ void cp16(uint32_t dst, const void* src) {
    asm volatile("cp.async.cg.shared.global [%0], [%1], 16;" :: "r"(dst), "l"(src) : "memory");
}
__device__ __forceinline__ void ldm_x4(uint32_t* r, uint32_t addr) {
    asm volatile("ldmatrix.sync.aligned.m8n8.x4.shared.b16 {%0,%1,%2,%3}, [%4];"
                 : "=r"(r[0]), "=r"(r[1]), "=r"(r[2]), "=r"(r[3]) : "r"(addr));
}
__device__ __forceinline__ void mma16816(float* c, const uint32_t* a, uint32_t b0, uint32_t b1) {
    asm volatile("mma.sync.aligned.m16n8k16.row.col.f32.f16.f16.f32 "
                 "{%0,%1,%2,%3}, {%4,%5,%6,%7}, {%8,%9}, {%0,%1,%2,%3};"
                 : "+f"(c[0]), "+f"(c[1]), "+f"(c[2]), "+f"(c[3])
                 : "r"(a[0]), "r"(a[1]), "r"(a[2]), "r"(a[3]), "r"(b0), "r"(b1));
}

// ---------------- device scratch (no runtime allocation allowed) ------------
__device__ __half g_A[NN * KDIM];           // M fp16, [o, i]            (2 MB)
__device__ __half g_X[BB * DS * KDIM];      // xT fp16, [(b*128+ds), i] (16 MB)

// ---------------- prep 1: M fp32 -> fp16 ------------------------------------
__global__ void conv_M(const float* __restrict__ M) {
    int i = blockIdx.x * 256 + threadIdx.x;
    g_A[i] = __float2half_rn(M[i]);
}

// ---------------- prep 2: transpose x[b,i,ds] -> g_X[(b*128+ds), i] ---------
__global__ void transpose_x(const float* __restrict__ x) {
    __shared__ float t[32][33];
    const int b  = blockIdx.z;
    const int i0 = blockIdx.x * 32;
    const int d0 = blockIdx.y * 32;
    const int tx = threadIdx.x, ty = threadIdx.y;     // 32 x 8
#pragma unroll
    for (int r = ty; r < 32; r += 8)
        t[r][tx] = x[(size_t)b * (NN * DS) + (size_t)(i0 + r) * DS + (d0 + tx)];
    __syncthreads();
#pragma unroll
    for (int r = ty; r < 32; r += 8)
        g_X[(size_t)(b * DS + d0 + r) * KDIM + i0 + tx] = __float2half_rn(t[tx][r]);
}

// ---------------- GEMM + fused dendrite/soma epilogue -----------------------
// Grid (8, 64): 128-o tile x batch. Block 256 = 8 warps, warp tile m64 x n32
// (warp layout 2 m-warps x 4 n-warps). Double-buffered cp.async, SW128 smem.
// smem: stage s: A tile at s*32768 (16KB, 128 rows x 128B), B at +16384.
// Epilogue reuses smem as C[128][129] f32 + 256 partial-soma floats.
__global__ void __launch_bounds__(256) gemm_neuron(
    const float* __restrict__ w_syn,    // [N, 128]
    const float* __restrict__ b_dend,   // [N, 8]
    const float* __restrict__ w_dend,   // [N, 8]
    const float* __restrict__ b_soma,   // [N]
    float* __restrict__ out)            // [B, N]
{
    extern __shared__ char smem[];
    const uint32_t sb = smem_u32(smem);
    const int tid  = threadIdx.x;
    const int wid  = tid >> 5, lane = tid & 31;
    const int wm   = wid & 1;          // m-warp (0..1) -> 64 rows
    const int wn   = wid >> 1;         // n-warp (0..3) -> 32 cols
    const int o0   = blockIdx.x * 128;
    const int b    = blockIdx.y;

    // ---- precompute swizzled ldmatrix lane offsets (constant-indexed) ----
    uint32_t offA[4][4], offB[4][2];
#pragma unroll
    for (int kb = 0; kb < 4; kb++) {
#pragma unroll
        for (int mt = 0; mt < 4; mt++) {
            uint32_t m = wm * 64 + mt * 16 + (lane & 15);
            uint32_t k = kb * 16 + (lane >> 4) * 8;
            offA[kb][mt] = SWZ(m * 128 + k * 2);
        }
#pragma unroll
        for (int bt = 0; bt < 2; bt++) {
            uint32_t n = wn * 32 + bt * 16 + ((lane >> 4) & 1) * 8 + (lane & 7);
            uint32_t k = kb * 16 + ((lane >> 3) & 1) * 8;
            offB[kb][bt] = SWZ(n * 128 + k * 2) + 16384;
        }
    }

    float acc[4][4][4];
#pragma unroll
    for (int mt = 0; mt < 4; mt++)
#pragma unroll
        for (int nt = 0; nt < 4; nt++)
#pragma unroll
            for (int q = 0; q < 4; q++) acc[mt][nt][q] = 0.f;

    const __half* gA = g_A + (size_t)o0 * KDIM;
    const __half* gB = g_X + (size_t)b * DS * KDIM;

    // stage loader: thread t copies 4 x 16B per operand
#define STAGE(c) do {                                                          \
    const uint32_t _base = sb + ((c) & 1) * 32768;                             \
    _Pragma("unroll")                                                          \
    for (int j = 0; j < 4; j++) {                                              \
        const int g   = tid + j * 256;                                         \
        const int row = g >> 3, col = g & 7;                                   \
        const uint32_t d = SWZ((uint32_t)(row * 128 + col * 16));              \
        cp16(_base + d,         gA + (size_t)row * KDIM + (c) * CHUNK + col * 8); \
        cp16(_base + 16384 + d, gB + (size_t)row * KDIM + (c) * CHUNK + col * 8); \
    }                                                                          \
    asm volatile("cp.async.commit_group;" ::: "memory");                       \
} while (0)

    STAGE(0);
    for (int c = 0; c < NCH; c++) {
        if (c + 1 < NCH) {
            STAGE(c + 1);
            asm volatile("cp.async.wait_group 1;" ::: "memory");
        } else {
            asm volatile("cp.async.wait_group 0;" ::: "memory");
        }
        __syncthreads();

        const uint32_t base = sb + (c & 1) * 32768;
#pragma unroll
        for (int kb = 0; kb < 4; kb++) {
            uint32_t a[4][4], bf[2][4];
#pragma unroll
            for (int mt = 0; mt < 4; mt++) ldm_x4(a[mt], base + offA[kb][mt]);
#pragma unroll
            for (int bt = 0; bt < 2; bt++) ldm_x4(bf[bt], base + offB[kb][bt]);
#pragma unroll
            for (int mt = 0; mt < 4; mt++)
#pragma unroll
                for (int nt = 0; nt < 4; nt++)
                    mma16816(acc[mt][nt], a[mt],
                             bf[nt >> 1][(nt & 1) * 2], bf[nt >> 1][(nt & 1) * 2 + 1]);
        }
        __syncthreads();   // done reading this buffer before it is re-staged
    }

    // ---- epilogue: accum -> smem C[128][129], then fused neuron math ----
    float* C = (float*)smem;           // row stride 129 floats (conflict-free)
#pragma unroll
    for (int mt = 0; mt < 4; mt++)
#pragma unroll
        for (int nt = 0; nt < 4; nt++) {
            const int r  = wm * 64 + mt * 16 + (lane >> 2);
            const int cc = wn * 32 + nt * 8 + (lane & 3) * 2;
            C[r * 129 + cc]           = acc[mt][nt][0];
            C[r * 129 + cc + 1]       = acc[mt][nt][1];
            C[(r + 8) * 129 + cc]     = acc[mt][nt][2];
            C[(r + 8) * 129 + cc + 1] = acc[mt][nt][3];
        }
    __syncthreads();

    // 2 threads per o-row: thread = (h, row), h selects ds half [h*64, h*64+64)
    const int row = tid & 127;
    const int h   = tid >> 7;
    const int o   = o0 + row;
    float td[4] = {0.f, 0.f, 0.f, 0.f};
    const float4* w4 = (const float4*)(w_syn + (size_t)o * 128 + h * 64);
#pragma unroll
    for (int j4 = 0; j4 < 16; j4++) {
        const float4 w = w4[j4];
        const int e = h * 64 + j4 * 4;
        const int d = j4 >> 2;                     // dendrite within half
        td[d] += C[row * 129 + e]     * w.x
               + C[row * 129 + e + 1] * w.y
               + C[row * 129 + e + 2] * w.z
               + C[row * 129 + e + 3] * w.w;
    }
    float sh = 0.f;
#pragma unroll
    for (int d = 0; d < 4; d++) {
        const int dd = h * 4 + d;
        sh += tanhf(td[d] + b_dend[o * 8 + dd]) * w_dend[o * 8 + dd];
    }
    float* spart = (float*)(smem + 128 * 129 * 4);
    spart[h * 128 + row] = sh;
    __syncthreads();
    if (tid < 128) {
        const float s = spart[tid] + spart[128 + tid] + b_soma[o0 + tid];
        out[b * NN + o0 + tid] = 1.0f / (1.0f + expf(-s));
    }
}

// ---------------------------------------------------------------------------
extern "C" void kernel_launch(void* const* d_in, const int* in_sizes, int n_in,
                              void* d_out, int out_size)
{
    const float* x      = (const float*)d_in[0];   // [B, N, D, S]
    const float* M      = (const float*)d_in[1];   // [N, N]
    const float* w_syn  = (const float*)d_in[2];   // [N, D, S]
    const float* b_dend = (const float*)d_in[3];   // [N, D]
    const float* w_dend = (const float*)d_in[4];   // [N, D]
    const float* b_soma = (const float*)d_in[5];   // [N]
    float* out          = (float*)d_out;           // [B, N]

    const int SMEM = 128 * 129 * 4 + 256 * 4;      // 67072 (> 2*32768 pipeline)
    cudaFuncSetAttribute(gemm_neuron, cudaFuncAttributeMaxDynamicSharedMemorySize, SMEM);

    conv_M<<<(NN * NN) / 256, 256>>>(M);
    transpose_x<<<dim3(NN / 32, DS / 32, BB), dim3(32, 8)>>>(x);
    gemm_neuron<<<dim3(NN / 128, BB), 256, SMEM>>>(w_syn, b_dend, w_dend, b_soma, out);
}